// round 4
// baseline (speedup 1.0000x reference)
#include <cuda_runtime.h>

#define BB 2
#define NN 384
#define HID 512
#define RD 256
#define R2 128
#define R4 64
#define NH 8
#define ROWS (BB*NN)              // 768
#define TJ 32
#define TILES (ROWS*(NN/TJ))      // 9216

// ---------------- scratch ----------------
__device__ float g_q[ROWS*RD];
__device__ float g_k[ROWS*RD];
__device__ float g_v[ROWS*HID];
__device__ float g_att[(size_t)ROWS*NN*NH];
__device__ float g_out1p[4][ROWS*HID];

__device__ __forceinline__ float warp_sum(float v){
  #pragma unroll
  for (int o=16;o;o>>=1) v += __shfl_xor_sync(0xffffffffu, v, o);
  return v;
}
typedef unsigned long long ull;
__device__ __forceinline__ ull fma2(ull a, ull b, ull c){
  ull d;
  asm("fma.rn.f32x2 %0, %1, %2, %3;" : "=l"(d) : "l"(a), "l"(b), "l"(c));
  return d;
}
__device__ __forceinline__ ull pack2(float x){
  ull d;
  asm("mov.b64 %0, {%1, %1};" : "=l"(d) : "f"(x));
  return d;
}
__device__ __forceinline__ float lo2(ull v){ return __uint_as_float((unsigned)v); }
__device__ __forceinline__ float hi2(ull v){ return __uint_as_float((unsigned)(v>>32)); }

// ---------------- kernel A ----------------
__global__ void __launch_bounds__(256) kA(const float* __restrict__ node,
    const float* __restrict__ g0, const float* __restrict__ b0,
    const float* __restrict__ Wq, const float* __restrict__ bq,
    const float* __restrict__ Wk, const float* __restrict__ bk,
    const float* __restrict__ Wv, const float* __restrict__ bv)
{
  __shared__ float xs[8][HID];
  int tid = threadIdx.x, w = tid>>5, lane = tid&31;
  int r0 = blockIdx.x*8;
  {
    const float* np = node + (size_t)(r0+w)*HID;
    float vals[16]; float s=0.f, q2=0.f;
    #pragma unroll
    for (int u=0;u<16;++u){ float v = np[lane+32*u]; vals[u]=v; s+=v; q2+=v*v; }
    s = warp_sum(s); q2 = warp_sum(q2);
    float m = s*(1.f/HID);
    float rstd = rsqrtf(q2*(1.f/HID) - m*m + 1e-5f);
    #pragma unroll
    for (int u=0;u<16;++u){ int c = lane+32*u; xs[w][c] = fmaxf((vals[u]-m)*rstd*g0[c]+b0[c], 0.f); }
  }
  __syncthreads();
  float aq[8], ak[8], av0[8], av1[8];
  #pragma unroll
  for (int rr=0;rr<8;++rr){aq[rr]=0.f;ak[rr]=0.f;av0[rr]=0.f;av1[rr]=0.f;}
  #pragma unroll 4
  for (int h=0; h<HID; ++h){
    float wq = Wq[h*RD+tid], wk = Wk[h*RD+tid];
    float wv0 = Wv[h*HID+tid], wv1 = Wv[h*HID+tid+256];
    #pragma unroll
    for (int rr=0;rr<8;++rr){
      float x = xs[rr][h];
      aq[rr] += x*wq; ak[rr] += x*wk; av0[rr] += x*wv0; av1[rr] += x*wv1;
    }
  }
  #pragma unroll
  for (int rr=0;rr<8;++rr){
    g_q[(r0+rr)*RD+tid]  = aq[rr]+bq[tid];
    g_k[(r0+rr)*RD+tid]  = ak[rr]+bk[tid];
    g_v[(r0+rr)*HID+tid]      = av0[rr]+bv[tid];
    g_v[(r0+rr)*HID+tid+256]  = av1[rr]+bv[tid+256];
  }
}

// ---------------- kernel B: pair-MLP, lane=pair transposed layout ----------------
#define NTB 512
// smem float offsets
#define OF_W1   0
#define OF_W2   32768
#define OF_W3   40960
#define OF_DIR  41472
#define OF_L1G  42240
#define OF_L1B  42496
#define OF_B1   42752
#define OF_L2G  42880
#define OF_L2B  43008
#define OF_B2   43136
#define OF_L3G  43200
#define OF_L3B  43264
#define OF_B3   43328
#define OF_RELT 43440            // 256*33 = 8448 ; later: lrT(+0) / scratch(+4096)
#define OF_H1T  51888            // 128*33 = 4224 ; LN1 partials / a3T
#define SM_TOT  56112            // floats -> 224448 bytes

__global__ void __launch_bounds__(512) kB(
    const float* __restrict__ edge, const float* __restrict__ lrel_in,
    const int* __restrict__ drctn, const float* __restrict__ rmask,
    const float* __restrict__ ln1g, const float* __restrict__ ln1b,
    const float* __restrict__ W1, const float* __restrict__ b1,
    const float* __restrict__ ln2g, const float* __restrict__ ln2b,
    const float* __restrict__ W2, const float* __restrict__ b2,
    const float* __restrict__ dirW,
    const float* __restrict__ ln3g, const float* __restrict__ ln3b,
    const float* __restrict__ W3, const float* __restrict__ b3,
    float* __restrict__ lrel_out)
{
  extern __shared__ float sm[];
  float* W1s = sm + OF_W1;
  float* W2s = sm + OF_W2;
  float* W3s = sm + OF_W3;
  float* dirs= sm + OF_DIR;
  float* l1g = sm + OF_L1G; float* l1b = sm + OF_L1B; float* b1s = sm + OF_B1;
  float* l2g = sm + OF_L2G; float* l2b = sm + OF_L2B; float* b2s = sm + OF_B2;
  float* l3g = sm + OF_L3G; float* l3b = sm + OF_L3B; float* b3s = sm + OF_B3;
  float* relT = sm + OF_RELT;
  float* h1T  = sm + OF_H1T;
  float* lrT  = relT;            // after GEMM1, relT region reused
  float* scr  = relT + 4096;     // scratch: LN2/LN3 partials, GEMM3 partials
  float* a3T  = h1T;             // after GEMM2, h1T region reused
  float* p1s  = h1T;             // LN1 partials (before GEMM1)
  float* p1q  = h1T + 512;

  int tid = threadIdx.x;
  for (int i=tid; i<32768; i+=NTB) W1s[i]=W1[i];
  for (int i=tid; i<8192;  i+=NTB) W2s[i]=W2[i];
  for (int i=tid; i<512;   i+=NTB) W3s[i]=W3[i];
  for (int i=tid; i<768;   i+=NTB) dirs[i]=dirW[i];
  if (tid<256){ l1g[tid]=ln1g[tid]; l1b[tid]=ln1b[tid]; }
  if (tid<128){ b1s[tid]=b1[tid]; l2g[tid]=ln2g[tid]; l2b[tid]=ln2b[tid]; }
  if (tid<64){  b2s[tid]=b2[tid]; l3g[tid]=ln3g[tid]; l3b[tid]=ln3b[tid]; }
  if (tid<8)    b3s[tid]=b3[tid];

  int w = tid>>5, lane = tid&31;

  for (int tl = blockIdx.x; tl < TILES; tl += gridDim.x){
    int bi = tl/(NN/TJ);
    int j0 = (tl%(NN/TJ))*TJ;
    int brow = (bi/NN)*NN;
    __syncthreads();    // protects relT/scr reuse across tiles (and covers weight load)

    // phase 1: relT[c][t] = q_i[c]*k_j[c] + edge + dir_emb[d]
    {
      int c = tid & 255, half = tid >> 8;
      float qv = g_q[bi*RD + c];
      const float* kp = g_k + (size_t)(brow + j0 + half*16)*RD + c;
      const float* ep = edge + ((size_t)bi*NN + j0 + half*16)*RD + c;
      const int*   dp = drctn + (size_t)bi*NN + j0 + half*16;
      float* rT = relT + c*33 + half*16;
      #pragma unroll 4
      for (int t0=0;t0<16;++t0){
        float kv = kp[(size_t)t0*RD];
        float ev = ep[(size_t)t0*RD];
        int d = dp[t0];                 // broadcast LDG (L1-hit)
        float dv = dirs[d*RD + c];
        rT[t0] = qv*kv + ev + dv;
      }
    }
    __syncthreads();

    // LN1 partials: warp w covers channels [w*16, w*16+16), lane = pair
    {
      float s=0.f,q2=0.f;
      const float* rp = relT + w*16*33 + lane;
      #pragma unroll
      for (int u=0;u<16;++u){ float v = rp[u*33]; s+=v; q2+=v*v; }
      p1s[w*32+lane]=s; p1q[w*32+lane]=q2;
    }
    __syncthreads();
    // redundant per-warp reduce (lane = pair) + normalize relT in place
    {
      float s=0.f,q2=0.f;
      #pragma unroll
      for (int u=0;u<16;++u){ s+=p1s[u*32+lane]; q2+=p1q[u*32+lane]; }
      float m = s*(1.f/RD);
      float rstd = rsqrtf(q2*(1.f/RD)-m*m+1e-5f);
      #pragma unroll
      for (int i=0;i<16;++i){
        int r = w + 16*i;
        float v = relT[r*33+lane];
        relT[r*33+lane] = (v-m)*rstd*l1g[r]+l1b[r];
      }
    }
    __syncthreads();

    // GEMM1: warp w -> cols [w*8, w*8+8), lane = pair; h1T = relu(. @ W1 + b1)
    {
      int c0 = w*8;
      ull acc0=0,acc1=0,acc2=0,acc3=0;
      const float* ap = relT + lane;
      const float* wp = W1s + c0;
      #pragma unroll 8
      for (int k=0;k<RD;++k){
        ull a2 = pack2(ap[k*33]);
        ulonglong2 w01 = *(const ulonglong2*)(wp + k*R2);
        ulonglong2 w23 = *(const ulonglong2*)(wp + k*R2 + 4);
        acc0=fma2(a2,w01.x,acc0); acc1=fma2(a2,w01.y,acc1);
        acc2=fma2(a2,w23.x,acc2); acc3=fma2(a2,w23.y,acc3);
      }
      float v0=lo2(acc0),v1=hi2(acc0),v2=lo2(acc1),v3=hi2(acc1);
      float v4=lo2(acc2),v5=hi2(acc2),v6=lo2(acc3),v7=hi2(acc3);
      h1T[(c0+0)*33+lane]=fmaxf(v0+b1s[c0+0],0.f);
      h1T[(c0+1)*33+lane]=fmaxf(v1+b1s[c0+1],0.f);
      h1T[(c0+2)*33+lane]=fmaxf(v2+b1s[c0+2],0.f);
      h1T[(c0+3)*33+lane]=fmaxf(v3+b1s[c0+3],0.f);
      h1T[(c0+4)*33+lane]=fmaxf(v4+b1s[c0+4],0.f);
      h1T[(c0+5)*33+lane]=fmaxf(v5+b1s[c0+5],0.f);
      h1T[(c0+6)*33+lane]=fmaxf(v6+b1s[c0+6],0.f);
      h1T[(c0+7)*33+lane]=fmaxf(v7+b1s[c0+7],0.f);
    }
    __syncthreads();

    // LN2 partials: warp w covers channels [w*8, w*8+8)
    {
      float s=0.f,q2=0.f;
      const float* hp = h1T + w*8*33 + lane;
      #pragma unroll
      for (int u=0;u<8;++u){ float v = hp[u*33]; s+=v; q2+=v*v; }
      scr[w*32+lane]=s; scr[512+w*32+lane]=q2;
    }
    __syncthreads();
    {
      float s=0.f,q2=0.f;
      #pragma unroll
      for (int u=0;u<16;++u){ s+=scr[u*32+lane]; q2+=scr[512+u*32+lane]; }
      float m = s*(1.f/R2);
      float rstd = rsqrtf(q2*(1.f/R2)-m*m+1e-5f);
      #pragma unroll
      for (int i=0;i<8;++i){
        int r = w + 16*i;
        float v = h1T[r*33+lane];
        h1T[r*33+lane] = (v-m)*rstd*l2g[r]+l2b[r];
      }
    }
    __syncthreads();

    // GEMM2: warp w -> cols [w*4, w*4+4); add last_relation; write global + lrT
    {
      int c0 = w*4;
      ull acc0=0, acc1=0;
      const float* ap = h1T + lane;
      const float* wp = W2s + c0;
      #pragma unroll 8
      for (int k=0;k<R2;++k){
        ull a2 = pack2(ap[k*33]);
        ulonglong2 wv = *(const ulonglong2*)(wp + k*R4);
        acc0=fma2(a2,wv.x,acc0); acc1=fma2(a2,wv.y,acc1);
      }
      size_t base = ((size_t)bi*NN + j0 + lane)*R4 + c0;
      float4 lrin = *(const float4*)(lrel_in + base);
      float4 o;
      o.x = lo2(acc0)+b2s[c0+0]+lrin.x;
      o.y = hi2(acc0)+b2s[c0+1]+lrin.y;
      o.z = lo2(acc1)+b2s[c0+2]+lrin.z;
      o.w = hi2(acc1)+b2s[c0+3]+lrin.w;
      *(float4*)(lrel_out + base) = o;
      lrT[(c0+0)*33+lane]=o.x;
      lrT[(c0+1)*33+lane]=o.y;
      lrT[(c0+2)*33+lane]=o.z;
      lrT[(c0+3)*33+lane]=o.w;
    }
    __syncthreads();

    // LN3 partials over relu(lrT): warp w covers channels [w*4, w*4+4)
    {
      float s=0.f,q2=0.f;
      const float* lp = lrT + w*4*33 + lane;
      #pragma unroll
      for (int u=0;u<4;++u){ float v = fmaxf(lp[u*33],0.f); s+=v; q2+=v*v; }
      scr[w*32+lane]=s; scr[512+w*32+lane]=q2;
    }
    __syncthreads();
    {
      float s=0.f,q2=0.f;
      #pragma unroll
      for (int u=0;u<16;++u){ s+=scr[u*32+lane]; q2+=scr[512+u*32+lane]; }
      float m = s*(1.f/R4);
      float rstd = rsqrtf(q2*(1.f/R4)-m*m+1e-5f);
      #pragma unroll
      for (int i=0;i<4;++i){
        int r = w + 16*i;
        float v = fmaxf(lrT[r*33+lane],0.f);
        a3T[r*33+lane] = (v-m)*rstd*l3g[r]+l3b[r];
      }
    }
    __syncthreads();

    // GEMM3 partials: warp w covers k in [w*4, w*4+4), 8 heads, lane = pair
    {
      ull acc0=0,acc1=0,acc2=0,acc3=0;
      #pragma unroll
      for (int u=0;u<4;++u){
        int k = w*4+u;
        ull a2 = pack2(a3T[k*33+lane]);
        ulonglong2 w01 = *(const ulonglong2*)(W3s + k*NH);
        ulonglong2 w23 = *(const ulonglong2*)(W3s + k*NH + 4);
        acc0=fma2(a2,w01.x,acc0); acc1=fma2(a2,w01.y,acc1);
        acc2=fma2(a2,w23.x,acc2); acc3=fma2(a2,w23.y,acc3);
      }
      ull* p3 = (ull*)scr;
      p3[(w*32+lane)*4+0]=acc0;
      p3[(w*32+lane)*4+1]=acc1;
      p3[(w*32+lane)*4+2]=acc2;
      p3[(w*32+lane)*4+3]=acc3;
    }
    __syncthreads();
    if (tid < 256){
      int t = tid>>3, hh = tid&7;
      float acc=0.f;
      #pragma unroll
      for (int u=0;u<16;++u) acc += scr[(u*32+t)*8 + hh];
      size_t ib = ((size_t)bi*NN + j0 + t)*NH + hh;
      g_att[ib] = acc + b3s[hh] + rmask[ib];
    }
  }
}

// ---------------- kernel C: softmax over j ----------------
__global__ void __launch_bounds__(256) kC()
{
  __shared__ float s[NN*NH];
  int bi = blockIdx.x, tid=threadIdx.x;
  float* g = g_att + (size_t)bi*NN*NH;
  for (int i=tid;i<NN*NH;i+=256) s[i]=g[i];
  __syncthreads();
  int w=tid>>5, lane=tid&31;
  float mx=-3.4e38f;
  float e[12];
  #pragma unroll
  for (int u=0;u<12;++u) mx = fmaxf(mx, s[(lane+32*u)*NH + w]);
  #pragma unroll
  for (int o=16;o;o>>=1) mx = fmaxf(mx, __shfl_xor_sync(0xffffffffu,mx,o));
  float sum=0.f;
  #pragma unroll
  for (int u=0;u<12;++u){ e[u]=__expf(s[(lane+32*u)*NH+w]-mx); sum+=e[u]; }
  sum = warp_sum(sum);
  float inv = 1.f/sum;
  #pragma unroll
  for (int u=0;u<12;++u) s[(lane+32*u)*NH+w] = e[u]*inv;
  __syncthreads();
  for (int i=tid;i<NN*NH;i+=256) g[i]=s[i];
}

// ---------------- kernel D: partial attn*V over j-splits ----------------
__global__ void __launch_bounds__(256) kD()
{
  __shared__ float as[4][32*NH];
  int tid=threadIdx.x;
  int row0 = blockIdx.x*4;
  int js = blockIdx.y;
  int b = row0/NN;
  int h0 = tid>>6;
  float acc0[4], acc1[4];
  #pragma unroll
  for (int rr=0;rr<4;++rr){acc0[rr]=0.f;acc1[rr]=0.f;}
  for (int jc=0;jc<3;++jc){
    int jb = js*96 + jc*32;
    __syncthreads();
    for (int idx=tid; idx<4*32*NH; idx+=256){
      int rr=idx>>8, rest=idx&255;
      as[rr][rest] = g_att[((size_t)(row0+rr)*NN + jb)*NH + rest];
    }
    __syncthreads();
    #pragma unroll 4
    for (int jj=0;jj<32;++jj){
      const float* vp = g_v + (size_t)(b*NN + jb+jj)*HID;
      float v0=vp[tid], v1=vp[tid+256];
      #pragma unroll
      for (int rr=0;rr<4;++rr){
        acc0[rr]+=as[rr][jj*NH+h0]*v0;
        acc1[rr]+=as[rr][jj*NH+h0+4]*v1;
      }
    }
  }
  #pragma unroll
  for (int rr=0;rr<4;++rr){
    g_out1p[js][(row0+rr)*HID + tid]     = acc0[rr];
    g_out1p[js][(row0+rr)*HID + tid+256] = acc1[rr];
  }
}

// ---------------- kernel E: out = (sum_js out1p) @ Wo + bo ----------------
__global__ void __launch_bounds__(256) kE(const float* __restrict__ Wo,
                                          const float* __restrict__ bo,
                                          float* __restrict__ out)
{
  __shared__ float ys[8][HID];
  int tid=threadIdx.x; int r0=blockIdx.x*8;
  for (int idx=tid; idx<8*HID; idx+=256){
    size_t base=(size_t)r0*HID+idx;
    ys[idx>>9][idx&511] = g_out1p[0][base]+g_out1p[1][base]+g_out1p[2][base]+g_out1p[3][base];
  }
  __syncthreads();
  float a0[8],a1[8];
  #pragma unroll
  for (int rr=0;rr<8;++rr){a0[rr]=0.f;a1[rr]=0.f;}
  #pragma unroll 4
  for (int h=0;h<HID;++h){
    float w0=Wo[h*HID+tid], w1=Wo[h*HID+tid+256];
    #pragma unroll
    for (int rr=0;rr<8;++rr){ float x=ys[rr][h]; a0[rr]+=x*w0; a1[rr]+=x*w1; }
  }
  #pragma unroll
  for (int rr=0;rr<8;++rr){
    out[(r0+rr)*HID+tid]     = a0[rr]+bo[tid];
    out[(r0+rr)*HID+tid+256] = a1[rr]+bo[tid+256];
  }
}

// ---------------- launch ----------------
extern "C" void kernel_launch(void* const* d_in, const int* in_sizes, int n_in,
                              void* d_out, int out_size)
{
  const float* node        = (const float*)d_in[0];
  const float* edge        = (const float*)d_in[1];
  const float* last_rel_in = (const float*)d_in[2];
  const int* drctn         = (const int*)d_in[3];
  const float* rel_mask    = (const float*)d_in[4];
  const float* ln0_g=(const float*)d_in[5];  const float* ln0_b=(const float*)d_in[6];
  const float* Wq=(const float*)d_in[7];     const float* bq=(const float*)d_in[8];
  const float* Wk=(const float*)d_in[9];     const float* bk=(const float*)d_in[10];
  const float* Wv=(const float*)d_in[11];    const float* bv=(const float*)d_in[12];
  const float* ln1_g=(const float*)d_in[13]; const float* ln1_b=(const float*)d_in[14];
  const float* W1=(const float*)d_in[15];    const float* b1=(const float*)d_in[16];
  const float* ln2_g=(const float*)d_in[17]; const float* ln2_b=(const float*)d_in[18];
  const float* W2=(const float*)d_in[19];    const float* b2=(const float*)d_in[20];
  const float* dir_emb=(const float*)d_in[21];
  const float* ln3_g=(const float*)d_in[22]; const float* ln3_b=(const float*)d_in[23];
  const float* W3=(const float*)d_in[24];    const float* b3=(const float*)d_in[25];
  const float* Wo=(const float*)d_in[26];    const float* bo=(const float*)d_in[27];

  float* out = (float*)d_out;
  const size_t LRELN = (size_t)BB*NN*NN*R4;
  float* lrel_out = out + ((size_t)out_size - LRELN);

  kA<<<ROWS/8,256>>>(node, ln0_g, ln0_b, Wq,bq,Wk,bk,Wv,bv);

  const int SMEM_B = SM_TOT*4;   // 224448 bytes
  cudaFuncSetAttribute(kB, cudaFuncAttributeMaxDynamicSharedMemorySize, SMEM_B);
  kB<<<152,512,SMEM_B>>>(edge, last_rel_in, drctn, rel_mask,
                         ln1_g, ln1_b, W1, b1, ln2_g, ln2_b, W2, b2,
                         dir_emb, ln3_g, ln3_b, W3, b3, lrel_out);

  kC<<<ROWS,256>>>();
  kD<<<dim3(192,4),256>>>();
  kE<<<ROWS/8,256>>>(Wo, bo, out);
}

// round 6
// speedup vs baseline: 1.3542x; 1.3542x over previous
#include <cuda_runtime.h>

#define BB 2
#define NN 384
#define HID 512
#define RD 256
#define R2 128
#define R4 64
#define NH 8
#define ROWS (BB*NN)              // 768
#define TJ 32
#define TILES (ROWS*(NN/TJ))      // 9216

// ---------------- scratch ----------------
__device__ float g_q[ROWS*RD];
__device__ float g_k[ROWS*RD];
__device__ float g_v[ROWS*HID];
__device__ float g_att[(size_t)ROWS*NN*NH];
__device__ float g_out1p[4][ROWS*HID];

__device__ __forceinline__ float warp_sum(float v){
  #pragma unroll
  for (int o=16;o;o>>=1) v += __shfl_xor_sync(0xffffffffu, v, o);
  return v;
}
typedef unsigned long long ull;
__device__ __forceinline__ ull fma2(ull a, ull b, ull c){
  ull d;
  asm("fma.rn.f32x2 %0, %1, %2, %3;" : "=l"(d) : "l"(a), "l"(b), "l"(c));
  return d;
}
__device__ __forceinline__ ull pack2(float x){
  ull d;
  asm("mov.b64 %0, {%1, %1};" : "=l"(d) : "f"(x));
  return d;
}
__device__ __forceinline__ float lo2(ull v){ return __uint_as_float((unsigned)v); }
__device__ __forceinline__ float hi2(ull v){ return __uint_as_float((unsigned)(v>>32)); }

// dummy kernel to shift the ncu capture slot onto kB
__global__ void kNop(){}

// ---------------- kernel A ----------------
__global__ void __launch_bounds__(256) kA(const float* __restrict__ node,
    const float* __restrict__ g0, const float* __restrict__ b0,
    const float* __restrict__ Wq, const float* __restrict__ bq,
    const float* __restrict__ Wk, const float* __restrict__ bk,
    const float* __restrict__ Wv, const float* __restrict__ bv)
{
  __shared__ float xs[8][HID];
  int tid = threadIdx.x, w = tid>>5, lane = tid&31;
  int r0 = blockIdx.x*8;
  {
    const float* np = node + (size_t)(r0+w)*HID;
    float vals[16]; float s=0.f, q2=0.f;
    #pragma unroll
    for (int u=0;u<16;++u){ float v = np[lane+32*u]; vals[u]=v; s+=v; q2+=v*v; }
    s = warp_sum(s); q2 = warp_sum(q2);
    float m = s*(1.f/HID);
    float rstd = rsqrtf(q2*(1.f/HID) - m*m + 1e-5f);
    #pragma unroll
    for (int u=0;u<16;++u){ int c = lane+32*u; xs[w][c] = fmaxf((vals[u]-m)*rstd*g0[c]+b0[c], 0.f); }
  }
  __syncthreads();
  float aq[8], ak[8], av0[8], av1[8];
  #pragma unroll
  for (int rr=0;rr<8;++rr){aq[rr]=0.f;ak[rr]=0.f;av0[rr]=0.f;av1[rr]=0.f;}
  #pragma unroll 4
  for (int h=0; h<HID; ++h){
    float wq = Wq[h*RD+tid], wk = Wk[h*RD+tid];
    float wv0 = Wv[h*HID+tid], wv1 = Wv[h*HID+tid+256];
    #pragma unroll
    for (int rr=0;rr<8;++rr){
      float x = xs[rr][h];
      aq[rr] += x*wq; ak[rr] += x*wk; av0[rr] += x*wv0; av1[rr] += x*wv1;
    }
  }
  #pragma unroll
  for (int rr=0;rr<8;++rr){
    g_q[(r0+rr)*RD+tid]  = aq[rr]+bq[tid];
    g_k[(r0+rr)*RD+tid]  = ak[rr]+bk[tid];
    g_v[(r0+rr)*HID+tid]      = av0[rr]+bv[tid];
    g_v[(r0+rr)*HID+tid+256]  = av1[rr]+bv[tid+256];
  }
}

// ---------------- kernel B: pair-MLP (R3 structure + fused LN + prefetch) ----------------
#define NTB 512
__global__ void __launch_bounds__(512) kB(
    const float* __restrict__ edge, const float* __restrict__ lrel_in,
    const int* __restrict__ drctn, const float* __restrict__ rmask,
    const float* __restrict__ ln1g, const float* __restrict__ ln1b,
    const float* __restrict__ W1, const float* __restrict__ b1,
    const float* __restrict__ ln2g, const float* __restrict__ ln2b,
    const float* __restrict__ W2, const float* __restrict__ b2,
    const float* __restrict__ dirW,
    const float* __restrict__ ln3g, const float* __restrict__ ln3b,
    const float* __restrict__ W3, const float* __restrict__ b3,
    float* __restrict__ lrel_out)
{
  extern __shared__ float sm[];
  float* W1s = sm;                 // 32768
  float* W2s = W1s + 32768;        // 8192
  float* W3s = W2s + 8192;         // 512
  float* dirs = W3s + 512;         // 768
  float* l1g = dirs + 768;         // 256
  float* l1b = l1g + 256;          // 256
  float* b1s = l1b + 256;          // 128
  float* l2g = b1s + 128;          // 128
  float* l2b = l2g + 128;          // 128
  float* b2s = l2b + 128;          // 64
  float* l3g = b2s + 64;           // 64
  float* l3b = l3g + 64;           // 64
  float* b3s = l3b + 64;           // 8
  float* qs  = b3s + 8;            // 256
  int*   dj  = (int*)(qs + 256);   // 64 (32 used)
  float* rel = (float*)(dj + 64);  // 8192 (later: lr[0:2048], a3[2048:4096], scratch[4096:8192])
  float* h1  = rel + 8192;         // 4096
  // total 55992 floats = 223968 B

  int tid = threadIdx.x;
  for (int i=tid; i<32768; i+=NTB) W1s[i]=W1[i];
  for (int i=tid; i<8192;  i+=NTB) W2s[i]=W2[i];
  for (int i=tid; i<512;   i+=NTB) W3s[i]=W3[i];
  for (int i=tid; i<768;   i+=NTB) dirs[i]=dirW[i];
  if (tid<256){ l1g[tid]=ln1g[tid]; l1b[tid]=ln1b[tid]; }
  if (tid<128){ b1s[tid]=b1[tid]; l2g[tid]=ln2g[tid]; l2b[tid]=ln2b[tid]; }
  if (tid<64){  b2s[tid]=b2[tid]; l3g[tid]=ln3g[tid]; l3b[tid]=ln3b[tid]; }
  if (tid<8)    b3s[tid]=b3[tid];

  int w = tid>>5, lane = tid&31;
  int og = w>>1, ks = w&1;             // 8 output groups x 2 K-splits

  for (int tl = blockIdx.x; tl < TILES; tl += gridDim.x){
    int bi = tl/(NN/TJ);
    int j0 = (tl%(NN/TJ))*TJ;
    int brow = (bi/NN)*NN;
    __syncthreads();                   // protects smem reuse across tiles

    if (tid<256) qs[tid] = g_q[bi*RD+tid];
    if (tid<TJ) dj[tid] = drctn[(size_t)bi*NN + j0 + tid];

    // prefetch DRAM operands consumed in late phases
    float2 lrin_pf[4];
    if (ks==0){
      #pragma unroll
      for (int p=0;p<4;++p){
        size_t base = ((size_t)bi*NN + j0 + 4*og + p)*R4 + 2*lane;
        lrin_pf[p] = *(const float2*)(lrel_in + base);
      }
    }
    float rm_pf = 0.f;
    size_t ib_pf = 0;
    if (tid < 256){
      int t = tid>>3, hh = tid&7;
      ib_pf = ((size_t)bi*NN + j0 + t)*NH + hh;
      rm_pf = rmask[ib_pf];
    }
    __syncthreads();

    // phase 1: rel = q_i * k_j + edge + dir_emb[d]
    {
      int half = tid>>8, c = tid&255;
      float qv = qs[c];
      const float* kp = g_k + (size_t)(brow + j0 + half*16)*RD + c;
      const float* ep = edge + ((size_t)bi*NN + j0 + half*16)*RD + c;
      float* rp = rel + (half*16)*RD + c;
      #pragma unroll 4
      for (int t0=0;t0<16;++t0){
        float kv = kp[(size_t)t0*RD];
        float ev = ep[(size_t)t0*RD];
        float dv = dirs[dj[half*16+t0]*RD + c];
        rp[t0*RD] = qv*kv + ev + dv;
      }
    }
    __syncthreads();

    // LN1 fused stats+normalize: warp w owns pairs 2w, 2w+1
    #pragma unroll
    for (int p=0;p<2;++p){
      int t = 2*w+p;
      float v[8]; float s=0.f,q2=0.f;
      #pragma unroll
      for (int u=0;u<8;++u){ v[u] = rel[t*RD + lane+32*u]; s+=v[u]; q2+=v[u]*v[u]; }
      s=warp_sum(s); q2=warp_sum(q2);
      float m = s*(1.f/RD);
      float rstd = rsqrtf(q2*(1.f/RD)-m*m+1e-5f);
      #pragma unroll
      for (int u=0;u<8;++u){
        int r = lane+32*u;
        rel[t*RD + r] = (v[u]-m)*rstd*l1g[r]+l1b[r];
      }
    }
    __syncthreads();

    // GEMM1: h1 = relu(LNrel @ W1 + b1). warp tile = 4 pairs x 128 cols, split-K (ks).
    {
      ull acc[4][2];
      #pragma unroll
      for (int p=0;p<4;++p){ acc[p][0]=0ull; acc[p][1]=0ull; }
      int rbase = ks*128;
      const float* rp = rel + (4*og)*RD;
      #pragma unroll 2
      for (int rb=rbase; rb<rbase+128; rb+=4){
        float a4[4][4];
        #pragma unroll
        for (int p=0;p<4;++p) *(float4*)a4[p] = *(const float4*)(rp + p*RD + rb);
        #pragma unroll
        for (int k=0;k<4;++k){
          ulonglong2 wv = *(const ulonglong2*)(W1s + (rb+k)*R2 + 4*lane);
          #pragma unroll
          for (int p=0;p<4;++p){
            ull a = pack2(a4[p][k]);
            acc[p][0] = fma2(a, wv.x, acc[p][0]);
            acc[p][1] = fma2(a, wv.y, acc[p][1]);
          }
        }
      }
      if (ks==1){
        #pragma unroll
        for (int p=0;p<4;++p){
          ulonglong2 v; v.x=acc[p][0]; v.y=acc[p][1];
          *(ulonglong2*)(h1 + (4*og+p)*R2 + 4*lane) = v;
        }
      }
      __syncthreads();
      if (ks==0){
        int c0=4*lane;
        #pragma unroll
        for (int p=0;p<4;++p){
          int t=4*og+p;
          float4 part = *(const float4*)(h1 + t*R2 + c0);
          float4 o;
          o.x=fmaxf(lo2(acc[p][0])+part.x+b1s[c0  ],0.f);
          o.y=fmaxf(hi2(acc[p][0])+part.y+b1s[c0+1],0.f);
          o.z=fmaxf(lo2(acc[p][1])+part.z+b1s[c0+2],0.f);
          o.w=fmaxf(hi2(acc[p][1])+part.w+b1s[c0+3],0.f);
          *(float4*)(h1 + t*R2 + c0) = o;
        }
      }
    }
    __syncthreads();

    // LN2 fused: warp w owns pairs 2w, 2w+1
    #pragma unroll
    for (int p=0;p<2;++p){
      int t=2*w+p;
      float v[4]; float s=0.f,q2=0.f;
      #pragma unroll
      for (int u=0;u<4;++u){ v[u]=h1[t*R2+lane+32*u]; s+=v[u]; q2+=v[u]*v[u]; }
      s=warp_sum(s); q2=warp_sum(q2);
      float m = s*(1.f/R2);
      float rstd = rsqrtf(q2*(1.f/R2)-m*m+1e-5f);
      #pragma unroll
      for (int u=0;u<4;++u){
        int r = lane+32*u;
        h1[t*R2+r]=(v[u]-m)*rstd*l2g[r]+l2b[r];
      }
    }
    __syncthreads();

    // GEMM2 + add last_relation; warp tile = 4 pairs x 64 cols, split-K.
    float* lr  = rel;            // [0,2048)
    float* a3  = rel + 2048;     // [2048,4096)
    float* g2s = rel + 4096;     // [4096,6144) partials
    {
      ull acc[4];
      #pragma unroll
      for (int p=0;p<4;++p) acc[p]=0ull;
      int rbase = ks*64;
      const float* hp = h1 + (4*og)*R2;
      #pragma unroll 2
      for (int rb=rbase; rb<rbase+64; rb+=4){
        float a4[4][4];
        #pragma unroll
        for (int p=0;p<4;++p) *(float4*)a4[p] = *(const float4*)(hp + p*R2 + rb);
        #pragma unroll
        for (int k=0;k<4;++k){
          ull wv = *(const ull*)(W2s + (rb+k)*R4 + 2*lane);
          #pragma unroll
          for (int p=0;p<4;++p) acc[p] = fma2(pack2(a4[p][k]), wv, acc[p]);
        }
      }
      if (ks==1){
        #pragma unroll
        for (int p=0;p<4;++p)
          *(ull*)(g2s + (4*og+p)*R4 + 2*lane) = acc[p];
      }
      __syncthreads();
      if (ks==0){
        int c0=2*lane;
        #pragma unroll
        for (int p=0;p<4;++p){
          int t=4*og+p;
          ull part = *(const ull*)(g2s + t*R4 + c0);
          size_t base = ((size_t)bi*NN + j0 + t)*R4 + c0;
          float2 o;
          o.x = lo2(acc[p])+lo2(part)+b2s[c0]  +lrin_pf[p].x;
          o.y = hi2(acc[p])+hi2(part)+b2s[c0+1]+lrin_pf[p].y;
          *(float2*)(lrel_out + base) = o;
          lr[t*R4+c0]=o.x; lr[t*R4+c0+1]=o.y;
        }
      }
    }
    __syncthreads();

    // LN3 fused on relu(last_rel): warp w owns pairs 2w, 2w+1; writes a3
    #pragma unroll
    for (int p=0;p<2;++p){
      int t=2*w+p;
      float v0=fmaxf(lr[t*R4+lane],0.f), v1=fmaxf(lr[t*R4+lane+32],0.f);
      float s=warp_sum(v0+v1), q2=warp_sum(v0*v0+v1*v1);
      float m = s*(1.f/R4);
      float rstd = rsqrtf(q2*(1.f/R4)-m*m+1e-5f);
      a3[t*R4+lane]    = (v0-m)*rstd*l3g[lane]+l3b[lane];
      a3[t*R4+lane+32] = (v1-m)*rstd*l3g[lane+32]+l3b[lane+32];
    }
    __syncthreads();

    // GEMM3 partials: warp w covers k in [w*4, w*4+4), 8 heads, lane = pair
    float* scr = rel + 4096;     // [4096,8192): 2048 ull partials (g2s dead now)
    {
      ull acc0=0,acc1=0,acc2=0,acc3=0;
      #pragma unroll
      for (int u=0;u<4;++u){
        int k = w*4+u;
        ull a2 = pack2(a3[lane*R4 + k]);
        ulonglong2 w01 = *(const ulonglong2*)(W3s + k*NH);
        ulonglong2 w23 = *(const ulonglong2*)(W3s + k*NH + 4);
        acc0=fma2(a2,w01.x,acc0); acc1=fma2(a2,w01.y,acc1);
        acc2=fma2(a2,w23.x,acc2); acc3=fma2(a2,w23.y,acc3);
      }
      ull* p3 = (ull*)scr;
      p3[(w*32+lane)*4+0]=acc0;
      p3[(w*32+lane)*4+1]=acc1;
      p3[(w*32+lane)*4+2]=acc2;
      p3[(w*32+lane)*4+3]=acc3;
    }
    __syncthreads();
    if (tid < 256){
      int t = tid>>3, hh = tid&7;
      float acc=0.f;
      #pragma unroll
      for (int u=0;u<16;++u) acc += scr[(u*32+t)*8 + hh];
      g_att[ib_pf] = acc + b3s[hh] + rm_pf;
    }
  }
}

// ---------------- kernel C: softmax over j ----------------
__global__ void __launch_bounds__(256) kC()
{
  __shared__ float s[NN*NH];
  int bi = blockIdx.x, tid=threadIdx.x;
  float* g = g_att + (size_t)bi*NN*NH;
  for (int i=tid;i<NN*NH;i+=256) s[i]=g[i];
  __syncthreads();
  int w=tid>>5, lane=tid&31;
  float mx=-3.4e38f;
  float e[12];
  #pragma unroll
  for (int u=0;u<12;++u) mx = fmaxf(mx, s[(lane+32*u)*NH + w]);
  #pragma unroll
  for (int o=16;o;o>>=1) mx = fmaxf(mx, __shfl_xor_sync(0xffffffffu,mx,o));
  float sum=0.f;
  #pragma unroll
  for (int u=0;u<12;++u){ e[u]=__expf(s[(lane+32*u)*NH+w]-mx); sum+=e[u]; }
  sum = warp_sum(sum);
  float inv = 1.f/sum;
  #pragma unroll
  for (int u=0;u<12;++u) s[(lane+32*u)*NH+w] = e[u]*inv;
  __syncthreads();
  for (int i=tid;i<NN*NH;i+=256) g[i]=s[i];
}

// ---------------- kernel D: partial attn*V over j-splits ----------------
__global__ void __launch_bounds__(256) kD()
{
  __shared__ float as[4][32*NH];
  int tid=threadIdx.x;
  int row0 = blockIdx.x*4;
  int js = blockIdx.y;
  int b = row0/NN;
  int h0 = tid>>6;
  float acc0[4], acc1[4];
  #pragma unroll
  for (int rr=0;rr<4;++rr){acc0[rr]=0.f;acc1[rr]=0.f;}
  for (int jc=0;jc<3;++jc){
    int jb = js*96 + jc*32;
    __syncthreads();
    for (int idx=tid; idx<4*32*NH; idx+=256){
      int rr=idx>>8, rest=idx&255;
      as[rr][rest] = g_att[((size_t)(row0+rr)*NN + jb)*NH + rest];
    }
    __syncthreads();
    #pragma unroll 4
    for (int jj=0;jj<32;++jj){
      const float* vp = g_v + (size_t)(b*NN + jb+jj)*HID;
      float v0=vp[tid], v1=vp[tid+256];
      #pragma unroll
      for (int rr=0;rr<4;++rr){
        acc0[rr]+=as[rr][jj*NH+h0]*v0;
        acc1[rr]+=as[rr][jj*NH+h0+4]*v1;
      }
    }
  }
  #pragma unroll
  for (int rr=0;rr<4;++rr){
    g_out1p[js][(row0+rr)*HID + tid]     = acc0[rr];
    g_out1p[js][(row0+rr)*HID + tid+256] = acc1[rr];
  }
}

// ---------------- kernel E ----------------
__global__ void __launch_bounds__(256) kE(const float* __restrict__ Wo,
                                          const float* __restrict__ bo,
                                          float* __restrict__ out)
{
  __shared__ float ys[8][HID];
  int tid=threadIdx.x; int r0=blockIdx.x*8;
  for (int idx=tid; idx<8*HID; idx+=256){
    size_t base=(size_t)r0*HID+idx;
    ys[idx>>9][idx&511] = g_out1p[0][base]+g_out1p[1][base]+g_out1p[2][base]+g_out1p[3][base];
  }
  __syncthreads();
  float a0[8],a1[8];
  #pragma unroll
  for (int rr=0;rr<8;++rr){a0[rr]=0.f;a1[rr]=0.f;}
  #pragma unroll 4
  for (int h=0;h<HID;++h){
    float w0=Wo[h*HID+tid], w1=Wo[h*HID+tid+256];
    #pragma unroll
    for (int rr=0;rr<8;++rr){ float x=ys[rr][h]; a0[rr]+=x*w0; a1[rr]+=x*w1; }
  }
  #pragma unroll
  for (int rr=0;rr<8;++rr){
    out[(r0+rr)*HID+tid]     = a0[rr]+bo[tid];
    out[(r0+rr)*HID+tid+256] = a1[rr]+bo[tid+256];
  }
}

// ---------------- launch ----------------
extern "C" void kernel_launch(void* const* d_in, const int* in_sizes, int n_in,
                              void* d_out, int out_size)
{
  const float* node        = (const float*)d_in[0];
  const float* edge        = (const float*)d_in[1];
  const float* last_rel_in = (const float*)d_in[2];
  const int* drctn         = (const int*)d_in[3];
  const float* rel_mask    = (const float*)d_in[4];
  const float* ln0_g=(const float*)d_in[5];  const float* ln0_b=(const float*)d_in[6];
  const float* Wq=(const float*)d_in[7];     const float* bq=(const float*)d_in[8];
  const float* Wk=(const float*)d_in[9];     const float* bk=(const float*)d_in[10];
  const float* Wv=(const float*)d_in[11];    const float* bv=(const float*)d_in[12];
  const float* ln1_g=(const float*)d_in[13]; const float* ln1_b=(const float*)d_in[14];
  const float* W1=(const float*)d_in[15];    const float* b1=(const float*)d_in[16];
  const float* ln2_g=(const float*)d_in[17]; const float* ln2_b=(const float*)d_in[18];
  const float* W2=(const float*)d_in[19];    const float* b2=(const float*)d_in[20];
  const float* dir_emb=(const float*)d_in[21];
  const float* ln3_g=(const float*)d_in[22]; const float* ln3_b=(const float*)d_in[23];
  const float* W3=(const float*)d_in[24];    const float* b3=(const float*)d_in[25];
  const float* Wo=(const float*)d_in[26];    const float* bo=(const float*)d_in[27];

  float* out = (float*)d_out;
  const size_t LRELN = (size_t)BB*NN*NN*R4;
  float* lrel_out = out + ((size_t)out_size - LRELN);

  kNop<<<1,32>>>();
  kNop<<<1,32>>>();

  kA<<<ROWS/8,256>>>(node, ln0_g, ln0_b, Wq,bq,Wk,bk,Wv,bv);

  const int SMEM_B = 55992*4;
  cudaFuncSetAttribute(kB, cudaFuncAttributeMaxDynamicSharedMemorySize, SMEM_B);
  kB<<<152,512,SMEM_B>>>(edge, last_rel_in, drctn, rel_mask,
                         ln1_g, ln1_b, W1, b1, ln2_g, ln2_b, W2, b2,
                         dir_emb, ln3_g, ln3_b, W3, b3, lrel_out);

  kC<<<ROWS,256>>>();
  kD<<<dim3(192,4),256>>>();
  kE<<<ROWS/8,256>>>(Wo, bo, out);
}